// round 12
// baseline (speedup 1.0000x reference)
#include <cuda_runtime.h>
#include <cstdint>

// ----------------------------------------------------------------------------
// GCN_8796093022507: 2-layer GCN, N=100000 nodes, E=6.4M edges.
// Scalar-per-node factorized form. JAX threefry (partitionable):
//   random_bits(32) elem j = y0 ^ y1 of threefry(key, (0, j))
//   split(key)[i]          = (y0, y1) of threefry(key, (0, i))
// edge_index int32 on device. Channel masks with relu(h)==0 can't affect the
// output -> compact nodes by sign(a) so the h>0 skip is warp-uniform.
// ----------------------------------------------------------------------------

#define N_MAX 100352

__device__ int   g_deg  [N_MAX];
__device__ float g_dinv [N_MAX];
__device__ float g_t1   [N_MAX];
__device__ float g_acc1 [N_MAX];
__device__ float g_a    [N_MAX];   // dinv*acc1 (layer-1 pre-activation scalar)
__device__ float g_t2   [N_MAX];
__device__ float g_acc2 [N_MAX];
__device__ int   g_cnt  [2];       // pos / neg list sizes
__device__ int   g_listP[N_MAX];
__device__ int   g_listN[N_MAX];

// --- JAX threefry2x32 (20 rounds) -------------------------------------------
__host__ __device__ inline void tf2x32(uint32_t k0, uint32_t k1,
                                       uint32_t x0, uint32_t x1,
                                       uint32_t& y0, uint32_t& y1)
{
    uint32_t ks2 = k0 ^ k1 ^ 0x1BD11BDAu;
    x0 += k0; x1 += k1;
#define TFR(r) { x0 += x1; x1 = (x1 << (r)) | (x1 >> (32 - (r))); x1 ^= x0; }
    TFR(13) TFR(15) TFR(26) TFR(6)
    x0 += k1;  x1 += ks2 + 1u;
    TFR(17) TFR(29) TFR(16) TFR(24)
    x0 += ks2; x1 += k0 + 2u;
    TFR(13) TFR(15) TFR(26) TFR(6)
    x0 += k0;  x1 += k1 + 3u;
    TFR(17) TFR(29) TFR(16) TFR(24)
    x0 += k1;  x1 += ks2 + 4u;
    TFR(13) TFR(15) TFR(26) TFR(6)
    x0 += ks2; x1 += k0 + 5u;
#undef TFR
    y0 = x0; y1 = x1;
}

__device__ __forceinline__ uint32_t rbits(uint32_t k0, uint32_t k1, uint32_t j) {
    uint32_t y0, y1;
    tf2x32(k0, k1, 0u, j, y0, y1);
    return y0 ^ y1;
}

__device__ __forceinline__ float u01(uint32_t bits) {
    return __uint_as_float((bits >> 9) | 0x3f800000u) - 1.0f;
}

// --- kernels ----------------------------------------------------------------

__global__ void k_zero(int N) {
    int i = blockIdx.x * blockDim.x + threadIdx.x;
    if (i < N) { g_deg[i] = 0; g_acc1[i] = 0.0f; g_acc2[i] = 0.0f; }
    if (i < 2) g_cnt[i] = 0;
}

// In-degree: 8 edges/thread, RED.S32
__global__ void k_deg(const int* __restrict__ dst, int E) {
    int base = (blockIdx.x * blockDim.x + threadIdx.x) * 8;
    if (base + 8 <= E) {
        int4 d0 = __ldg((const int4*)(dst + base));
        int4 d1 = __ldg((const int4*)(dst + base + 4));
        atomicAdd(&g_deg[d0.x], 1); atomicAdd(&g_deg[d0.y], 1);
        atomicAdd(&g_deg[d0.z], 1); atomicAdd(&g_deg[d0.w], 1);
        atomicAdd(&g_deg[d1.x], 1); atomicAdd(&g_deg[d1.y], 1);
        atomicAdd(&g_deg[d1.z], 1); atomicAdd(&g_deg[d1.w], 1);
    } else {
        for (int e = base; e < E; ++e)
            atomicAdd(&g_deg[__ldg(dst + e)], 1);
    }
}

// dinv + dropout1(x) + t1 = dinv*xd
__global__ void k_nodeA(const float* __restrict__ x, int N,
                        uint32_t k0, uint32_t k1) {
    int i = blockIdx.x * blockDim.x + threadIdx.x;
    if (i >= N) return;
    int dg = g_deg[i];
    float dv = (dg > 0) ? rsqrtf((float)dg) : 0.0f;
    g_dinv[i] = dv;
    float xv = __ldg(&x[i]);
    float xd = (u01(rbits(k0, k1, (uint32_t)i)) < 0.4f) ? xv / 0.4f : 0.0f;
    g_t1[i] = dv * xd;
}

// Edge aggregation: 8 edges/thread; 8 gathers in flight then 8 REDs
template <int PASS>
__global__ void k_agg(const int* __restrict__ src,
                      const int* __restrict__ dst, int E) {
    const float* __restrict__ t   = (PASS == 1) ? g_t1   : g_t2;
    float*       __restrict__ acc = (PASS == 1) ? g_acc1 : g_acc2;
    int base = (blockIdx.x * blockDim.x + threadIdx.x) * 8;
    if (base + 8 <= E) {
        int4 s0 = __ldg((const int4*)(src + base));
        int4 s1 = __ldg((const int4*)(src + base + 4));
        int4 d0 = __ldg((const int4*)(dst + base));
        int4 d1 = __ldg((const int4*)(dst + base + 4));
        float v0 = __ldg(&t[s0.x]);
        float v1 = __ldg(&t[s0.y]);
        float v2 = __ldg(&t[s0.z]);
        float v3 = __ldg(&t[s0.w]);
        float v4 = __ldg(&t[s1.x]);
        float v5 = __ldg(&t[s1.y]);
        float v6 = __ldg(&t[s1.z]);
        float v7 = __ldg(&t[s1.w]);
        atomicAdd(&acc[d0.x], v0); atomicAdd(&acc[d0.y], v1);
        atomicAdd(&acc[d0.z], v2); atomicAdd(&acc[d0.w], v3);
        atomicAdd(&acc[d1.x], v4); atomicAdd(&acc[d1.y], v5);
        atomicAdd(&acc[d1.z], v6); atomicAdd(&acc[d1.w], v7);
    } else {
        for (int e = base; e < E; ++e)
            atomicAdd(&acc[__ldg(dst + e)], __ldg(&t[__ldg(src + e)]));
    }
}

// Classify nodes by sign(a); a==0 -> t2=0 immediately. Warp-aggregated append.
__global__ void k_classify(int N) {
    int i = blockIdx.x * blockDim.x + threadIdx.x;
    if (i >= N) return;
    float a = g_dinv[i] * g_acc1[i];
    g_a[i] = a;
    bool pos = (a > 0.0f), neg = (a < 0.0f);
    if (!pos && !neg) g_t2[i] = 0.0f;

    unsigned amask = __activemask();
    unsigned mp = __ballot_sync(amask, pos);
    unsigned mn = __ballot_sync(amask, neg);
    int lane   = threadIdx.x & 31;
    int leader = __ffs(amask) - 1;
    int pB = 0, nB = 0;
    if (lane == leader) {
        if (mp) pB = atomicAdd(&g_cnt[0], __popc(mp));
        if (mn) nB = atomicAdd(&g_cnt[1], __popc(mn));
    }
    pB = __shfl_sync(amask, pB, leader);
    nB = __shfl_sync(amask, nB, leader);
    if (pos) g_listP[pB + __popc(mp & ((1u << lane) - 1u))] = i;
    if (neg) g_listN[nB + __popc(mn & ((1u << lane) - 1u))] = i;
}

// Layer-1 epilogue over one sign-homogeneous list: the h>0 test is
// warp-uniform (b1==0 in practice), so dead channels skip threefry entirely.
template <int SGN>
__global__ void k_nodeC(const float* __restrict__ W1, const float* __restrict__ b1,
                        const float* __restrict__ W2,
                        uint32_t k0, uint32_t k1) {
    int t = blockIdx.x * blockDim.x + threadIdx.x;
    if (t >= g_cnt[SGN]) return;
    const int* __restrict__ list = (SGN == 0) ? g_listP : g_listN;
    int   i = list[t];
    float a = g_a[i];
    float s = 0.0f;

#pragma unroll
    for (int c = 0; c < 16; ++c) {
        float h = fmaf(__ldg(&W1[c]), a, __ldg(&b1[c]));
        if (h > 0.0f) {   // relu gate: masks of dead channels are irrelevant
            if (u01(rbits(k0, k1, (uint32_t)i * 16u + (uint32_t)c)) < 0.4f)
                s += (h / 0.4f) * __ldg(&W2[c]);
        }
    }
    g_t2[i] = g_dinv[i] * s;
}

__global__ void k_nodeE(float* __restrict__ out, const float* __restrict__ b2, int N) {
    int i = blockIdx.x * blockDim.x + threadIdx.x;
    if (i < N) out[i] = g_dinv[i] * g_acc2[i] + __ldg(&b2[0]);
}

// --- launch -----------------------------------------------------------------

extern "C" void kernel_launch(void* const* d_in, const int* in_sizes, int n_in,
                              void* d_out, int out_size) {
    const float* x  = (const float*)d_in[0];
    const int*   ei = (const int*)d_in[1];     // int32 on device
    const float* W1 = (const float*)d_in[2];
    const float* b1 = (const float*)d_in[3];
    const float* W2 = (const float*)d_in[4];
    const float* b2 = (const float*)d_in[5];
    int N = in_sizes[0];
    int E = in_sizes[1] / 2;
    const int* src = ei;
    const int* dst = ei + E;

    // Foldlike split of key(42)=(0,42)
    uint32_t key1_0, key1_1, key2_0, key2_1;
    tf2x32(0u, 42u, 0u, 0u, key1_0, key1_1);   // dropout 1
    tf2x32(0u, 42u, 0u, 1u, key2_0, key2_1);   // dropout 2

    const int T = 256;
    int eThreads = (E + 7) / 8;
    unsigned eBlocks = (unsigned)((eThreads + T - 1) / T);
    unsigned nBlocks = (unsigned)((N + T - 1) / T);
    unsigned hBlocks = (unsigned)((N / 2 + 4096 + T - 1) / T);  // per-sign upper bound-ish

    k_zero    <<<nBlocks, T>>>(N);
    k_deg     <<<eBlocks, T>>>(dst, E);
    k_nodeA   <<<nBlocks, T>>>(x, N, key1_0, key1_1);
    k_agg<1>  <<<eBlocks, T>>>(src, dst, E);
    k_classify<<<nBlocks, T>>>(N);
    k_nodeC<0><<<nBlocks, T>>>(W1, b1, W2, key2_0, key2_1);
    k_nodeC<1><<<nBlocks, T>>>(W1, b1, W2, key2_0, key2_1);
    k_agg<2>  <<<eBlocks, T>>>(src, dst, E);
    k_nodeE   <<<nBlocks, T>>>((float*)d_out, b2, N);
    (void)hBlocks;
}

// round 15
// speedup vs baseline: 1.0410x; 1.0410x over previous
#include <cuda_runtime.h>
#include <cstdint>

// ----------------------------------------------------------------------------
// GCN_8796093022507: 2-layer GCN, N=100000 nodes, E=6.4M edges.
// Scalar-per-node factorized form. JAX threefry (partitionable):
//   random_bits(32) elem j = y0 ^ y1 of threefry(key, (0, j))
//   split(key)[i]          = (y0, y1) of threefry(key, (0, i))
// edge_index int32 on device. relu-dead channels can't affect the output ->
// compact nodes by sign(a) so the per-channel threefry skip is warp-uniform.
// ----------------------------------------------------------------------------

#define N_MAX 100352

__device__ int   g_deg  [N_MAX];
__device__ float g_dinv [N_MAX];
__device__ float g_t1   [N_MAX];
__device__ float g_acc1 [N_MAX];
__device__ float g_a    [N_MAX];   // dinv*acc1 (layer-1 pre-activation scalar)
__device__ float g_t2   [N_MAX];
__device__ float g_acc2 [N_MAX];
__device__ int   g_cnt  [2];       // pos / neg list sizes
__device__ int   g_listP[N_MAX];
__device__ int   g_listN[N_MAX];

// --- JAX threefry2x32 (20 rounds) -------------------------------------------
__host__ __device__ inline void tf2x32(uint32_t k0, uint32_t k1,
                                       uint32_t x0, uint32_t x1,
                                       uint32_t& y0, uint32_t& y1)
{
    uint32_t ks2 = k0 ^ k1 ^ 0x1BD11BDAu;
    x0 += k0; x1 += k1;
#define TFR(r) { x0 += x1; x1 = (x1 << (r)) | (x1 >> (32 - (r))); x1 ^= x0; }
    TFR(13) TFR(15) TFR(26) TFR(6)
    x0 += k1;  x1 += ks2 + 1u;
    TFR(17) TFR(29) TFR(16) TFR(24)
    x0 += ks2; x1 += k0 + 2u;
    TFR(13) TFR(15) TFR(26) TFR(6)
    x0 += k0;  x1 += k1 + 3u;
    TFR(17) TFR(29) TFR(16) TFR(24)
    x0 += k1;  x1 += ks2 + 4u;
    TFR(13) TFR(15) TFR(26) TFR(6)
    x0 += ks2; x1 += k0 + 5u;
#undef TFR
    y0 = x0; y1 = x1;
}

__device__ __forceinline__ uint32_t rbits(uint32_t k0, uint32_t k1, uint32_t j) {
    uint32_t y0, y1;
    tf2x32(k0, k1, 0u, j, y0, y1);
    return y0 ^ y1;
}

__device__ __forceinline__ float u01(uint32_t bits) {
    return __uint_as_float((bits >> 9) | 0x3f800000u) - 1.0f;
}

// --- kernels ----------------------------------------------------------------

__global__ void k_zero(int N) {
    int i = blockIdx.x * blockDim.x + threadIdx.x;
    if (i < N) { g_deg[i] = 0; g_acc1[i] = 0.0f; g_acc2[i] = 0.0f; }
    if (i < 2) g_cnt[i] = 0;
}

// In-degree: 4 edges/thread (R9-proven), RED.S32
__global__ void k_deg(const int* __restrict__ dst, int E) {
    int base = (blockIdx.x * blockDim.x + threadIdx.x) * 4;
    if (base + 4 <= E) {
        int4 d = __ldg((const int4*)(dst + base));
        atomicAdd(&g_deg[d.x], 1);
        atomicAdd(&g_deg[d.y], 1);
        atomicAdd(&g_deg[d.z], 1);
        atomicAdd(&g_deg[d.w], 1);
    } else {
        for (int e = base; e < E; ++e)
            atomicAdd(&g_deg[__ldg(dst + e)], 1);
    }
}

// dinv + dropout1(x) + t1 = dinv*xd
__global__ void k_nodeA(const float* __restrict__ x, int N,
                        uint32_t k0, uint32_t k1) {
    int i = blockIdx.x * blockDim.x + threadIdx.x;
    if (i >= N) return;
    int dg = g_deg[i];
    float dv = (dg > 0) ? rsqrtf((float)dg) : 0.0f;
    g_dinv[i] = dv;
    float xv = __ldg(&x[i]);
    float xd = (u01(rbits(k0, k1, (uint32_t)i)) < 0.4f) ? xv / 0.4f : 0.0f;
    g_t1[i] = dv * xd;
}

// Edge aggregation: 2 edges/thread (oe*MLP_p1 ~= Q_th -> minimal L1tex-queue spread)
template <int PASS>
__global__ void k_agg(const int* __restrict__ src,
                      const int* __restrict__ dst, int E) {
    const float* __restrict__ t   = (PASS == 1) ? g_t1   : g_t2;
    float*       __restrict__ acc = (PASS == 1) ? g_acc1 : g_acc2;
    int base = (blockIdx.x * blockDim.x + threadIdx.x) * 2;
    if (base + 2 <= E) {
        int2 s = __ldg((const int2*)(src + base));
        int2 d = __ldg((const int2*)(dst + base));
        float v0 = __ldg(&t[s.x]);
        float v1 = __ldg(&t[s.y]);
        atomicAdd(&acc[d.x], v0);
        atomicAdd(&acc[d.y], v1);
    } else {
        for (int e = base; e < E; ++e)
            atomicAdd(&acc[__ldg(dst + e)], __ldg(&t[__ldg(src + e)]));
    }
}

// Classify nodes by sign(a); a==0 -> t2=0 immediately. Warp-aggregated append.
__global__ void k_classify(int N) {
    int i = blockIdx.x * blockDim.x + threadIdx.x;
    if (i >= N) return;
    float a = g_dinv[i] * g_acc1[i];
    g_a[i] = a;
    bool pos = (a > 0.0f), neg = (a < 0.0f);
    if (!pos && !neg) g_t2[i] = 0.0f;

    unsigned amask = __activemask();
    unsigned mp = __ballot_sync(amask, pos);
    unsigned mn = __ballot_sync(amask, neg);
    int lane   = threadIdx.x & 31;
    int leader = __ffs(amask) - 1;
    int pB = 0, nB = 0;
    if (lane == leader) {
        if (mp) pB = atomicAdd(&g_cnt[0], __popc(mp));
        if (mn) nB = atomicAdd(&g_cnt[1], __popc(mn));
    }
    pB = __shfl_sync(amask, pB, leader);
    nB = __shfl_sync(amask, nB, leader);
    if (pos) g_listP[pB + __popc(mp & ((1u << lane) - 1u))] = i;
    if (neg) g_listN[nB + __popc(mn & ((1u << lane) - 1u))] = i;
}

// Layer-1 epilogue over one sign-homogeneous list: the h>0 test is
// warp-uniform (b1==0), so relu-dead channels skip threefry at issue level.
template <int SGN>
__global__ void k_nodeC(const float* __restrict__ W1, const float* __restrict__ b1,
                        const float* __restrict__ W2,
                        uint32_t k0, uint32_t k1) {
    int t = blockIdx.x * blockDim.x + threadIdx.x;
    if (t >= g_cnt[SGN]) return;
    const int* __restrict__ list = (SGN == 0) ? g_listP : g_listN;
    int   i = list[t];
    float a = g_a[i];
    float s = 0.0f;

#pragma unroll
    for (int c = 0; c < 16; ++c) {
        float h = fmaf(__ldg(&W1[c]), a, __ldg(&b1[c]));
        if (h > 0.0f) {   // warp-uniform within a sign-homogeneous list
            if (u01(rbits(k0, k1, (uint32_t)i * 16u + (uint32_t)c)) < 0.4f)
                s += (h / 0.4f) * __ldg(&W2[c]);
        }
    }
    g_t2[i] = g_dinv[i] * s;
}

__global__ void k_nodeE(float* __restrict__ out, const float* __restrict__ b2, int N) {
    int i = blockIdx.x * blockDim.x + threadIdx.x;
    if (i < N) out[i] = g_dinv[i] * g_acc2[i] + __ldg(&b2[0]);
}

// --- launch -----------------------------------------------------------------

extern "C" void kernel_launch(void* const* d_in, const int* in_sizes, int n_in,
                              void* d_out, int out_size) {
    const float* x  = (const float*)d_in[0];
    const int*   ei = (const int*)d_in[1];     // int32 on device
    const float* W1 = (const float*)d_in[2];
    const float* b1 = (const float*)d_in[3];
    const float* W2 = (const float*)d_in[4];
    const float* b2 = (const float*)d_in[5];
    int N = in_sizes[0];
    int E = in_sizes[1] / 2;
    const int* src = ei;
    const int* dst = ei + E;

    // Foldlike split of key(42)=(0,42)
    uint32_t key1_0, key1_1, key2_0, key2_1;
    tf2x32(0u, 42u, 0u, 0u, key1_0, key1_1);   // dropout 1
    tf2x32(0u, 42u, 0u, 1u, key2_0, key2_1);   // dropout 2

    const int T = 256;
    unsigned e4Blocks = (unsigned)(((E + 3) / 4 + T - 1) / T);
    unsigned e2Blocks = (unsigned)(((E + 1) / 2 + T - 1) / T);
    unsigned nBlocks  = (unsigned)((N + T - 1) / T);

    k_zero    <<<nBlocks, T>>>(N);
    k_deg     <<<e4Blocks, T>>>(dst, E);
    k_nodeA   <<<nBlocks, T>>>(x, N, key1_0, key1_1);
    k_agg<1>  <<<e2Blocks, T>>>(src, dst, E);
    k_classify<<<nBlocks, T>>>(N);
    k_nodeC<0><<<nBlocks, T>>>(W1, b1, W2, key2_0, key2_1);
    k_nodeC<1><<<nBlocks, T>>>(W1, b1, W2, key2_0, key2_1);
    k_agg<2>  <<<e2Blocks, T>>>(src, dst, E);
    k_nodeE   <<<nBlocks, T>>>((float*)d_out, b2, N);
}